// round 1
// baseline (speedup 1.0000x reference)
#include <cuda_runtime.h>
#include <math.h>

#define NBATCH 16
#define NANCH  3
#define FS     64
#define NPIX   (FS*FS)          // 4096
#define NCELL  (NBATCH*NANCH*NPIX)
#define NLAB   50
#define NCLS   80
#define NCH    85

// ---------------- device scratch (no allocation allowed) ----------------
__device__ float  g_tm[NCELL];
__device__ float  g_tscale[NCELL];
__device__ float  g_fx[NCELL];
__device__ float  g_fy[NCELL];
__device__ float  g_lw[NCELL];
__device__ float  g_lh[NCELL];
__device__ int    g_clsid[NCELL];
__device__ float4 g_tbox[NBATCH*NLAB];   // truth tlx,tly,brx,bry (grid units)
__device__ float  g_tarea[NBATCH*NLAB];  // tw*th
__device__ int    g_mlist[NBATCH*NLAB];  // unique matched cell indices
__device__ int    g_mcount;
__device__ double g_acc[4];              // 0=xy 1=wh 2=obj 3=cls

// ANCHORS / STRIDE
__constant__ float c_RW[9] = {1.25f,2.0f,4.125f,3.75f,7.75f,7.375f,14.5f,19.5f,46.625f};
__constant__ float c_RH[9] = {1.625f,3.75f,2.875f,7.625f,5.625f,14.875f,11.25f,24.75f,40.75f};

__device__ __forceinline__ float sigm(float x){ return 1.0f/(1.0f + expf(-x)); }

// Matches reference _bce: clip(p, 1e-12, 1-1e-12) where the upper bound rounds
// to 1.0f in fp32; log terms clamped at -100.
__device__ __forceinline__ float bcef(float p, float t){
    float pc = fminf(fmaxf(p, 1e-12f), 1.0f);
    float la = fmaxf(logf(pc),     -100.0f);
    float lb = fmaxf(log1pf(-pc),  -100.0f);
    return -(t*la + (1.0f - t)*lb);
}

__device__ __forceinline__ float warpsum(float v){
    #pragma unroll
    for (int o = 16; o; o >>= 1) v += __shfl_down_sync(0xffffffffu, v, o);
    return v;
}

// ---------------- kernel 1: clear per-launch state ----------------
__global__ void k_clear(){
    int i = blockIdx.x*blockDim.x + threadIdx.x;
    if (i < NCELL) g_tm[i] = 0.0f;
    if (i == 0) g_mcount = 0;
    if (i < 4)  g_acc[i] = 0.0;
}

// ---------------- kernel 2: label preprocessing (serial per batch = last-wins
// on duplicate scatter indices, matching XLA sequential scatter) ----------------
__global__ void k_setup(const float* __restrict__ labels){
    int b = threadIdx.x;
    if (b >= NBATCH) return;
    for (int k = 0; k < NLAB; k++){
        const float* L = labels + (size_t)(b*NLAB + k)*5;
        float cls = L[0], x = L[1], y = L[2], w = L[3], h = L[4];
        float tx = x*FS, ty = y*FS, tw = w*FS, th = h*FS;
        g_tbox[b*NLAB+k]  = make_float4(tx - tw*0.5f, ty - th*0.5f,
                                        tx + tw*0.5f, ty + th*0.5f);
        g_tarea[b*NLAB+k] = tw*th;
        // anchor-iou argmax over 9 reference anchors (first max wins)
        float best = -1e30f; int bi = 0;
        #pragma unroll
        for (int n = 0; n < 9; n++){
            float inter = fminf(tw, c_RW[n]) * fminf(th, c_RH[n]);
            float uni   = tw*th + c_RW[n]*c_RH[n] - inter;
            float iou   = inter/uni;
            if (iou > best){ best = iou; bi = n; }
        }
        bool valid = (cls + x + y + w + h) > 0.0f;
        if (valid && bi < NANCH){
            int ti = (int)tx, tj = (int)ty;
            int idx = ((b*NANCH + bi) << 12) + (tj << 6) + ti;
            if (g_tm[idx] == 0.0f){               // unique-cell list for cls kernel
                int s = atomicAdd(&g_mcount, 1);
                g_mlist[s] = idx;
            }
            g_tm[idx]     = 1.0f;
            g_tscale[idx] = 2.0f - tw*th*(1.0f/(float)(FS*FS));
            g_fx[idx]     = tx - (float)ti;
            g_fy[idx]     = ty - (float)tj;
            g_lw[idx]     = logf(tw / c_RW[bi] + 1e-16f);
            g_lh[idx]     = logf(th / c_RH[bi] + 1e-16f);
            g_clsid[idx]  = (int)cls;
        }
    }
}

// ---------------- kernel 3: fused conv(N=15) + IoU-ignore + obj/xy/wh losses ----
// grid: 16 blocks per batch image (256 pixels each), 256 threads, 1 pixel/thread.
__global__ __launch_bounds__(256) void k_main(const float* __restrict__ xin,
                                              const float* __restrict__ conv_w,
                                              const float* __restrict__ conv_b){
    __shared__ __align__(16) float Ws[256*16];   // Ws[c][s], s = a*5+j, pad s=15
    __shared__ float4 s_tb[NLAB];
    __shared__ float  s_ta[NLAB];
    __shared__ float  s_bias[16];
    __shared__ float  s_red[8][3];

    int tid = threadIdx.x;
    int b   = blockIdx.x >> 4;
    int pix = ((blockIdx.x & 15) << 8) + tid;

    // load the 15 needed weight rows, transposed into smem
    for (int i = tid; i < 15*256; i += 256){
        int s = i >> 8, c = i & 255;
        int a = s / 5, j = s - a*5;
        Ws[c*16 + s] = conv_w[(a*NCH + j)*256 + c];
    }
    for (int c = tid; c < 256; c += 256) Ws[c*16 + 15] = 0.0f;
    if (tid < 15){ int a = tid/5; s_bias[tid] = conv_b[a*NCH + (tid - a*5)]; }
    if (tid == 15) s_bias[15] = 0.0f;
    if (tid < NLAB){ s_tb[tid] = g_tbox[b*NLAB + tid]; s_ta[tid] = g_tarea[b*NLAB + tid]; }
    __syncthreads();

    float acc[16];
    #pragma unroll
    for (int s = 0; s < 16; s++) acc[s] = s_bias[s];

    const float*  xp = xin + (size_t)b*256*NPIX + pix;
    const float4* W4 = reinterpret_cast<const float4*>(Ws);
    #pragma unroll 4
    for (int c = 0; c < 256; c++){
        float  x  = xp[c*NPIX];
        float4 w0 = W4[c*4+0], w1 = W4[c*4+1], w2 = W4[c*4+2], w3 = W4[c*4+3];
        acc[ 0] += x*w0.x; acc[ 1] += x*w0.y; acc[ 2] += x*w0.z; acc[ 3] += x*w0.w;
        acc[ 4] += x*w1.x; acc[ 5] += x*w1.y; acc[ 6] += x*w1.z; acc[ 7] += x*w1.w;
        acc[ 8] += x*w2.x; acc[ 9] += x*w2.y; acc[10] += x*w2.z; acc[11] += x*w2.w;
        acc[12] += x*w3.x; acc[13] += x*w3.y; acc[14] += x*w3.z; acc[15] += x*w3.w;
    }

    const float MAW[3] = {1.25f, 2.0f, 4.125f};
    const float MAH[3] = {1.625f, 3.75f, 2.875f};
    float fw = (float)(pix & 63);
    float fh = (float)(pix >> 6);
    float lobj = 0.0f, lxy = 0.0f, lwh = 0.0f;

    #pragma unroll
    for (int a = 0; a < 3; a++){
        float o0 = acc[a*5+0], o1 = acc[a*5+1], o2 = acc[a*5+2];
        float o3 = acc[a*5+3], o4 = acc[a*5+4];
        float p0 = sigm(o0), p1 = sigm(o1), p4 = sigm(o4);
        float pw = expf(o2)*MAW[a], ph = expf(o3)*MAH[a];
        float px = p0 + fw, py = p1 + fh;
        float areaA = pw*ph;
        float ax0 = px - pw*0.5f, ay0 = py - ph*0.5f;
        float ax1 = px + pw*0.5f, ay1 = py + ph*0.5f;
        int ign = 0;
        for (int k = 0; k < NLAB; k++){
            float4 t  = s_tb[k];
            float iw  = fmaxf(fminf(ax1, t.z) - fmaxf(ax0, t.x), 0.0f);
            float ih  = fmaxf(fminf(ay1, t.w) - fmaxf(ay0, t.y), 0.0f);
            float inter = iw*ih;
            float den   = areaA + s_ta[k] - inter;
            ign |= (inter > 0.7f*den);   // iou > IGNORE_THRE, division-free
        }
        int idx = ((b*NANCH + a) << 12) + pix;
        float tmv = g_tm[idx];
        if (tmv != 0.0f){
            lobj += bcef(p4, 1.0f);
            float ts = g_tscale[idx];
            lxy += (bcef(p0, g_fx[idx]) + bcef(p1, g_fy[idx]))*ts;
            float dw = o2 - g_lw[idx], dh = o3 - g_lh[idx];
            lwh += (dw*dw + dh*dh)*0.5f*ts;
        } else if (!ign){
            lobj += bcef(p4, 0.0f);
        }
        // obj==0 & cls-at-unmatched terms are each ~1e-12 in the ref -> skipped
    }

    lxy = warpsum(lxy); lwh = warpsum(lwh); lobj = warpsum(lobj);
    int wid = tid >> 5, lane = tid & 31;
    if (lane == 0){ s_red[wid][0] = lxy; s_red[wid][1] = lwh; s_red[wid][2] = lobj; }
    __syncthreads();
    if (tid < 3){
        float v = 0.0f;
        #pragma unroll
        for (int wq = 0; wq < 8; wq++) v += s_red[wq][tid];
        atomicAdd(&g_acc[tid], (double)v);
    }
}

// ---------------- kernel 4: class loss only at matched cells (<=800 blocks) ----
__global__ __launch_bounds__(128) void k_cls(const float* __restrict__ xin,
                                             const float* __restrict__ conv_w,
                                             const float* __restrict__ conv_b){
    if ((int)blockIdx.x >= g_mcount) return;
    int idx = g_mlist[blockIdx.x];
    int b   = idx / (NANCH*NPIX);
    int r   = idx - b*(NANCH*NPIX);
    int a   = r >> 12;
    int pix = r & 4095;
    int cls = g_clsid[idx];

    __shared__ float xs[256];
    for (int c = threadIdx.x; c < 256; c += 128)
        xs[c] = xin[((size_t)b*256 + c)*NPIX + pix];
    __syncthreads();

    float lc = 0.0f;
    if (threadIdx.x < NCLS){
        int o = a*NCH + 5 + threadIdx.x;
        const float* wr = conv_w + (size_t)o*256;
        float av = conv_b[o];
        #pragma unroll 8
        for (int c = 0; c < 256; c++) av += xs[c]*wr[c];
        float p = sigm(av);
        float t = (threadIdx.x == cls) ? 1.0f : 0.0f;
        lc = bcef(p, t);
    }
    lc = warpsum(lc);
    __shared__ float s_r[4];
    if ((threadIdx.x & 31) == 0) s_r[threadIdx.x >> 5] = lc;
    __syncthreads();
    if (threadIdx.x == 0)
        atomicAdd(&g_acc[3], (double)(s_r[0] + s_r[1] + s_r[2] + s_r[3]));
}

// ---------------- kernel 5: finalize ----------------
__global__ void k_final(float* __restrict__ out){
    double xy = g_acc[0], wh = g_acc[1], obj = g_acc[2], cls = g_acc[3];
    out[0] = (float)(xy + wh + obj + cls);
    out[1] = (float)xy;
    out[2] = (float)wh;
    out[3] = (float)obj;
    out[4] = (float)cls;
}

extern "C" void kernel_launch(void* const* d_in, const int* in_sizes, int n_in,
                              void* d_out, int out_size){
    const float* xin    = (const float*)d_in[0];
    const float* labels = (const float*)d_in[1];
    const float* conv_w = (const float*)d_in[2];
    const float* conv_b = (const float*)d_in[3];
    float* out = (float*)d_out;

    k_clear<<<(NCELL + 255)/256, 256>>>();
    k_setup<<<1, 32>>>(labels);
    k_main<<<NBATCH*16, 256>>>(xin, conv_w, conv_b);
    k_cls<<<NBATCH*NLAB, 128>>>(xin, conv_w, conv_b);
    k_final<<<1, 1>>>(out);
}

// round 2
// speedup vs baseline: 1.6551x; 1.6551x over previous
#include <cuda_runtime.h>
#include <math.h>

#define NBATCH 16
#define NANCH  3
#define FS     64
#define NPIX   4096
#define NLAB   50
#define NCLS   80
#define NCH    85
#define CONVBLK 256         // 16 blocks/batch, 256 pixels each
#define LB      64          // per-batch match-list stride

// ---------------- device scratch ----------------
__device__ float4 g_tbox[NBATCH*NLAB];
__device__ float  g_tarea[NBATCH*NLAB];
__device__ int    g_lcnt[NBATCH];
__device__ int    g_lidx[NBATCH*LB];     // (a<<12)|pix
__device__ float4 g_ld4[NBATCH*LB];      // fx fy lw lh
__device__ float  g_lts[NBATCH*LB];      // tscale
__device__ int    g_mlist[NBATCH*NLAB];  // global cell index b*12288 + (a<<12|pix)
__device__ int    g_mcls[NBATCH*NLAB];
__device__ int    g_mcount;
__device__ double g_acc[4];              // xy wh obj cls

__constant__ float c_RW[9] = {1.25f,2.0f,4.125f,3.75f,7.75f,7.375f,14.5f,19.5f,46.625f};
__constant__ float c_RH[9] = {1.625f,3.75f,2.875f,7.625f,5.625f,14.875f,11.25f,24.75f,40.75f};

__device__ __forceinline__ float sigm(float x){ return 1.0f/(1.0f + expf(-x)); }

__device__ __forceinline__ float bcef(float p, float t){
    float pc = fminf(fmaxf(p, 1e-12f), 1.0f);
    float la = fmaxf(logf(pc),    -100.0f);
    float lb = fmaxf(log1pf(-pc), -100.0f);
    return -(t*la + (1.0f - t)*lb);
}

__device__ __forceinline__ float warpsum(float v){
    #pragma unroll
    for (int o = 16; o; o >>= 1) v += __shfl_down_sync(0xffffffffu, v, o);
    return v;
}

// packed fp32x2 helpers (Blackwell)
__device__ __forceinline__ unsigned long long packff(float a, float b){
    unsigned long long r;
    asm("mov.b64 %0, {%1, %2};" : "=l"(r) : "r"(__float_as_uint(a)), "r"(__float_as_uint(b)));
    return r;
}
__device__ __forceinline__ void unpackff(unsigned long long v, float& a, float& b){
    unsigned int lo, hi;
    asm("mov.b64 {%0, %1}, %2;" : "=r"(lo), "=r"(hi) : "l"(v));
    a = __uint_as_float(lo); b = __uint_as_float(hi);
}
#define FMA2(acc, a, b) asm("fma.rn.f32x2 %0, %1, %2, %0;" : "+l"(acc) : "l"(a), "l"(b))

// ---------------- kernel 1: setup (parallel candidates + per-batch serial dedup) ----
__global__ __launch_bounds__(1024) void k_setup(const float* __restrict__ labels){
    __shared__ int   s_vidx[NBATCH*NLAB];
    __shared__ float s_fx[NBATCH*NLAB], s_fy[NBATCH*NLAB];
    __shared__ float s_lw[NBATCH*NLAB], s_lh[NBATCH*NLAB], s_ts[NBATCH*NLAB];
    __shared__ int   s_c[NBATCH*NLAB];
    __shared__ int   s_list[NBATCH*NLAB];
    __shared__ int   s_lcls[NBATCH*NLAB];

    int tid = threadIdx.x;
    if (tid < NBATCH*NLAB){
        const float* L = labels + (size_t)tid*5;
        float cls = L[0], x = L[1], y = L[2], w = L[3], h = L[4];
        float tx = x*FS, ty = y*FS, tw = w*FS, th = h*FS;
        g_tbox[tid]  = make_float4(tx - tw*0.5f, ty - th*0.5f, tx + tw*0.5f, ty + th*0.5f);
        g_tarea[tid] = tw*th;
        float best = -1e30f; int bi = 0;
        #pragma unroll
        for (int n = 0; n < 9; n++){
            float inter = fminf(tw, c_RW[n]) * fminf(th, c_RH[n]);
            float uni   = tw*th + c_RW[n]*c_RH[n] - inter;
            float iou   = inter/uni;
            if (iou > best){ best = iou; bi = n; }
        }
        bool valid = (cls + x + y + w + h) > 0.0f;
        int ti = (int)tx, tj = (int)ty;
        s_vidx[tid] = (valid && bi < NANCH) ? ((bi<<12)|(tj<<6)|ti) : -1;
        s_fx[tid] = tx - (float)ti;
        s_fy[tid] = ty - (float)tj;
        s_lw[tid] = logf(tw / c_RW[bi < NANCH ? bi : 0] + 1e-16f);
        s_lh[tid] = logf(th / c_RH[bi < NANCH ? bi : 0] + 1e-16f);
        s_ts[tid] = 2.0f - tw*th*(1.0f/(float)(FS*FS));
        s_c[tid]  = (int)cls;
    }
    if (tid == 1023) g_mcount = 0;
    if (tid >= 1019 && tid < 1023) g_acc[tid-1019] = 0.0;
    __syncthreads();

    if (tid < NBATCH){
        int b = tid, cnt = 0;
        for (int k = 0; k < NLAB; k++){
            int c = b*NLAB + k;
            int idx = s_vidx[c];
            if (idx < 0) continue;
            int slot = -1;
            for (int j = 0; j < cnt; j++) if (s_list[b*NLAB+j] == idx) slot = j;
            if (slot < 0){ slot = cnt++; s_list[b*NLAB+slot] = idx; }
            s_lcls[b*NLAB+slot] = s_c[c];
            g_lidx[b*LB+slot] = idx;
            g_ld4 [b*LB+slot] = make_float4(s_fx[c], s_fy[c], s_lw[c], s_lh[c]);
            g_lts [b*LB+slot] = s_ts[c];
        }
        g_lcnt[b] = cnt;
        int base = atomicAdd(&g_mcount, cnt);
        for (int j = 0; j < cnt; j++){
            g_mlist[base+j] = b*(NANCH*NPIX) + s_list[b*NLAB+j];
            g_mcls [base+j] = s_lcls[b*NLAB+j];
        }
    }
}

// ---------------- kernel 2: fused conv(N=15)+losses  &  class loss ----------------
__global__ __launch_bounds__(256) void k_fused(const float* __restrict__ xin,
                                               const float* __restrict__ conv_w,
                                               const float* __restrict__ conv_b){
    __shared__ __align__(16) float Ws[256*16];
    __shared__ float4 s_tb[NLAB];
    __shared__ float  s_ta[NLAB];
    __shared__ float  s_bias[16];
    __shared__ int    s_lix[LB];
    __shared__ float4 s_l4[LB];
    __shared__ float  s_lt[LB];
    __shared__ int    s_cnt;
    __shared__ float  s_red[8][3];
    __shared__ float  s_cred[8];

    int tid = threadIdx.x;

    if (blockIdx.x >= CONVBLK){
        // ================= class-loss blocks =================
        int mb = (int)blockIdx.x - CONVBLK;
        if (mb >= g_mcount) return;
        int cell = g_mlist[mb];
        int cls  = g_mcls[mb];
        int b    = cell / (NANCH*NPIX);
        int r    = cell - b*(NANCH*NPIX);
        int a    = r >> 12;
        int pix  = r & 4095;
        int w    = tid >> 5, lane = tid & 31;

        const float* xb = xin + ((size_t)b*256)*NPIX + pix;
        float xv[8];
        #pragma unroll
        for (int i = 0; i < 8; i++) xv[i] = __ldg(xb + (size_t)(lane + (i<<5))*NPIX);

        float lc = 0.0f;
        #pragma unroll 2
        for (int t = 0; t < 10; t++){
            int c = w + (t<<3);                 // class 0..79
            int o = a*NCH + 5 + c;
            const float* wr = conv_w + (size_t)o*256;
            float s = 0.0f;
            #pragma unroll
            for (int i = 0; i < 8; i++) s += xv[i]*__ldg(wr + lane + (i<<5));
            s = warpsum(s);
            if (lane == 0){
                s += conv_b[o];
                lc += bcef(sigm(s), (c == cls) ? 1.0f : 0.0f);
            }
        }
        if (lane == 0) s_cred[w] = lc;
        __syncthreads();
        if (tid == 0){
            float v = 0.0f;
            #pragma unroll
            for (int q = 0; q < 8; q++) v += s_cred[q];
            atomicAdd(&g_acc[3], (double)v);
        }
        return;
    }

    // ================= conv + obj/xy/wh blocks =================
    int b   = blockIdx.x >> 4;
    int pix = ((blockIdx.x & 15) << 8) + tid;

    for (int i = tid; i < 15*256; i += 256){
        int s = i >> 8, c = i & 255;
        int a = s/5, j = s - a*5;
        Ws[c*16 + s] = conv_w[(a*NCH + j)*256 + c];
    }
    Ws[tid*16 + 15] = 0.0f;
    if (tid < 15){ int a = tid/5; s_bias[tid] = conv_b[a*NCH + (tid - a*5)]; }
    if (tid == 15) s_bias[15] = 0.0f;
    if (tid < NLAB){ s_tb[tid] = g_tbox[b*NLAB + tid]; s_ta[tid] = g_tarea[b*NLAB + tid]; }
    if (tid == 16) s_cnt = g_lcnt[b];
    if (tid >= 192){
        int j = tid - 192;
        s_lix[j] = g_lidx[b*LB + j];
        s_l4[j]  = g_ld4 [b*LB + j];
        s_lt[j]  = g_lts [b*LB + j];
    }
    __syncthreads();

    unsigned long long accd[8];
    #pragma unroll
    for (int p = 0; p < 8; p++) accd[p] = packff(s_bias[2*p], s_bias[2*p+1]);

    const float* xp = xin + (size_t)b*256*NPIX + pix;
    const ulonglong2* W2 = reinterpret_cast<const ulonglong2*>(Ws);
    #pragma unroll 4
    for (int c = 0; c < 256; c++){
        float x = xp[(size_t)c*NPIX];
        unsigned long long xd = packff(x, x);
        ulonglong2 q0 = W2[c*4+0], q1 = W2[c*4+1], q2 = W2[c*4+2], q3 = W2[c*4+3];
        FMA2(accd[0], xd, q0.x); FMA2(accd[1], xd, q0.y);
        FMA2(accd[2], xd, q1.x); FMA2(accd[3], xd, q1.y);
        FMA2(accd[4], xd, q2.x); FMA2(accd[5], xd, q2.y);
        FMA2(accd[6], xd, q3.x); FMA2(accd[7], xd, q3.y);
    }
    float acc[16];
    #pragma unroll
    for (int p = 0; p < 8; p++) unpackff(accd[p], acc[2*p], acc[2*p+1]);

    // which anchors match this pixel?
    int cnt = s_cnt;
    int msl[3] = {-1,-1,-1};
    for (int j = 0; j < cnt; j++){
        int e = s_lix[j];
        if ((e & 4095) == pix) msl[e >> 12] = j;
    }

    const float MAW[3] = {1.25f, 2.0f, 4.125f};
    const float MAH[3] = {1.625f, 3.75f, 2.875f};
    float fw = (float)(pix & 63);
    float fh = (float)(pix >> 6);
    float lobj = 0.0f, lxy = 0.0f, lwh = 0.0f;

    #pragma unroll
    for (int a = 0; a < 3; a++){
        float o0 = acc[a*5+0], o1 = acc[a*5+1], o2 = acc[a*5+2];
        float o3 = acc[a*5+3], o4 = acc[a*5+4];
        float p0 = sigm(o0), p1 = sigm(o1), p4 = sigm(o4);
        float pw = expf(o2)*MAW[a], ph = expf(o3)*MAH[a];
        float px = p0 + fw, py = p1 + fh;
        float areaA = pw*ph;
        float ax0 = px - pw*0.5f, ay0 = py - ph*0.5f;
        float ax1 = px + pw*0.5f, ay1 = py + ph*0.5f;
        int ign = 0;
        for (int k = 0; k < NLAB; k++){
            float4 t = s_tb[k];
            float iw = fmaxf(fminf(ax1, t.z) - fmaxf(ax0, t.x), 0.0f);
            float ih = fmaxf(fminf(ay1, t.w) - fmaxf(ay0, t.y), 0.0f);
            float inter = iw*ih;
            float den   = areaA + s_ta[k] - inter;
            ign |= (inter > 0.7f*den);
        }
        int slot = msl[a];
        if (slot >= 0){
            lobj += bcef(p4, 1.0f);
            float4 d = s_l4[slot];
            float ts = s_lt[slot];
            lxy += (bcef(p0, d.x) + bcef(p1, d.y))*ts;
            float dw = o2 - d.z, dh = o3 - d.w;
            lwh += (dw*dw + dh*dh)*0.5f*ts;
        } else if (!ign){
            lobj += bcef(p4, 0.0f);
        }
    }

    lxy = warpsum(lxy); lwh = warpsum(lwh); lobj = warpsum(lobj);
    int wid = tid >> 5, lane = tid & 31;
    if (lane == 0){ s_red[wid][0] = lxy; s_red[wid][1] = lwh; s_red[wid][2] = lobj; }
    __syncthreads();
    if (tid < 3){
        float v = 0.0f;
        #pragma unroll
        for (int q = 0; q < 8; q++) v += s_red[q][tid];
        atomicAdd(&g_acc[tid], (double)v);
    }
}

// ---------------- kernel 3: finalize ----------------
__global__ void k_final(float* __restrict__ out){
    double xy = g_acc[0], wh = g_acc[1], obj = g_acc[2], cls = g_acc[3];
    out[0] = (float)(xy + wh + obj + cls);
    out[1] = (float)xy;
    out[2] = (float)wh;
    out[3] = (float)obj;
    out[4] = (float)cls;
}

extern "C" void kernel_launch(void* const* d_in, const int* in_sizes, int n_in,
                              void* d_out, int out_size){
    const float* xin    = (const float*)d_in[0];
    const float* labels = (const float*)d_in[1];
    const float* conv_w = (const float*)d_in[2];
    const float* conv_b = (const float*)d_in[3];
    float* out = (float*)d_out;

    k_setup<<<1, 1024>>>(labels);
    k_fused<<<CONVBLK + NBATCH*NLAB, 256>>>(xin, conv_w, conv_b);
    k_final<<<1, 1>>>(out);
}

// round 4
// speedup vs baseline: 1.7182x; 1.0381x over previous
#include <cuda_runtime.h>
#include <math.h>

#define NBATCH 16
#define NANCH  3
#define FS     64
#define NPIX   4096
#define NLAB   50
#define NCLS   80
#define NCH    85
#define CLSBLK (NBATCH*NLAB)        // 800 class-loss blocks (one per label)
#define CONVBLK 256                 // 16 blocks/batch * 16 batches
#define TOTBLK (CLSBLK + CONVBLK)   // 1056

// ---------------- device scratch ----------------
__device__ float4 g_part[TOTBLK];   // per-block partials: x=xy y=wh z=obj w=cls

__constant__ float c_RW[9] = {1.25f,2.0f,4.125f,3.75f,7.75f,7.375f,14.5f,19.5f,46.625f};
__constant__ float c_RH[9] = {1.625f,3.75f,2.875f,7.625f,5.625f,14.875f,11.25f,24.75f,40.75f};

__device__ __forceinline__ float sigm(float x){ return 1.0f/(1.0f + expf(-x)); }

__device__ __forceinline__ float bcef(float p, float t){
    float pc = fminf(fmaxf(p, 1e-12f), 1.0f);
    float la = fmaxf(logf(pc),    -100.0f);
    float lb = fmaxf(log1pf(-pc), -100.0f);
    return -(t*la + (1.0f - t)*lb);
}

__device__ __forceinline__ float warpsum(float v){
    #pragma unroll
    for (int o = 16; o; o >>= 1) v += __shfl_down_sync(0xffffffffu, v, o);
    return v;
}

// packed fp32x2 helpers (Blackwell)
__device__ __forceinline__ unsigned long long packff(float a, float b){
    unsigned long long r;
    asm("mov.b64 %0, {%1, %2};" : "=l"(r) : "r"(__float_as_uint(a)), "r"(__float_as_uint(b)));
    return r;
}
__device__ __forceinline__ void unpackff(unsigned long long v, float& a, float& b){
    unsigned int lo, hi;
    asm("mov.b64 {%0, %1}, %2;" : "=r"(lo), "=r"(hi) : "l"(v));
    a = __uint_as_float(lo); b = __uint_as_float(hi);
}
#define FMA2(acc, a, b) asm("fma.rn.f32x2 %0, %1, %2, %0;" : "+l"(acc) : "l"(a), "l"(b))

// candidate cell index for one label (or -1)
__device__ __forceinline__ int label_idx(const float* __restrict__ L,
                                         float& tx, float& ty, float& tw, float& th,
                                         int& bi){
    float cls = L[0], x = L[1], y = L[2], w = L[3], h = L[4];
    tx = x*FS; ty = y*FS; tw = w*FS; th = h*FS;
    float best = -1e30f; bi = 0;
    #pragma unroll
    for (int n = 0; n < 9; n++){
        float inter = fminf(tw, c_RW[n]) * fminf(th, c_RH[n]);
        float uni   = tw*th + c_RW[n]*c_RH[n] - inter;
        float iou   = inter/uni;
        if (iou > best){ best = iou; bi = n; }
    }
    bool valid = (cls + x + y + w + h) > 0.0f;
    if (!(valid && bi < NANCH)) return -1;
    int ti = (int)tx, tj = (int)ty;
    return (bi<<12)|(tj<<6)|ti;
}

// ---------------- fused kernel: 800 cls blocks + 256 conv blocks ----------------
__global__ __launch_bounds__(256) void k_fused(const float* __restrict__ xin,
                                               const float* __restrict__ labels,
                                               const float* __restrict__ conv_w,
                                               const float* __restrict__ conv_b){
    int tid = threadIdx.x;

    if (blockIdx.x < CLSBLK){
        // ================= class-loss block for label (b, k) =================
        int mb = blockIdx.x;
        int b  = mb / NLAB, k = mb - b*NLAB;

        __shared__ int   s_idx[NLAB];
        __shared__ int   s_win;
        __shared__ float xs[256];
        __shared__ float s_wred[8];

        if (tid < NLAB){
            float tx,ty,tw,th; int bi;
            s_idx[tid] = label_idx(labels + (size_t)(b*NLAB + tid)*5, tx,ty,tw,th, bi);
        }
        __syncthreads();
        if (tid == 0){
            int idx = s_idx[k];
            if (idx >= 0)
                for (int j = k+1; j < NLAB; j++) if (s_idx[j] == idx) { idx = -1; break; }
            s_win = idx;
        }
        __syncthreads();
        int idx = s_win;
        if (idx < 0){
            if (tid == 0) g_part[blockIdx.x] = make_float4(0.f,0.f,0.f,0.f);
            return;
        }
        int a = idx >> 12, pix = idx & 4095;
        int cls = (int)labels[(size_t)(b*NLAB + k)*5];

        // one channel per thread (256 threads <-> 256 channels)
        xs[tid] = __ldg(xin + ((size_t)(b*256 + tid))*NPIX + pix);
        __syncthreads();

        int w = tid >> 5, lane = tid & 31;   // 8 warps x 10 classes = 80
        float lc = 0.0f;
        #pragma unroll 2
        for (int t = 0; t < 10; t++){
            int c = w + (t<<3);              // class 0..79
            int o = a*NCH + 5 + c;
            const float* wr = conv_w + (size_t)o*256;
            float s = 0.0f;
            #pragma unroll
            for (int i = 0; i < 8; i++) s += xs[lane + (i<<5)]*__ldg(wr + lane + (i<<5));
            s = warpsum(s);
            if (lane == 0){
                s += conv_b[o];
                lc += bcef(sigm(s), (c == cls) ? 1.0f : 0.0f);
            }
        }
        if (lane == 0) s_wred[w] = lc;
        __syncthreads();
        if (tid == 0){
            float v = 0.0f;
            #pragma unroll
            for (int q = 0; q < 8; q++) v += s_wred[q];
            g_part[blockIdx.x] = make_float4(0.f, 0.f, 0.f, v);
        }
        return;
    }

    // ================= conv + obj/xy/wh block =================
    int cb  = (int)blockIdx.x - CLSBLK;
    int b   = cb >> 4;
    int pix = ((cb & 15) << 8) + tid;

    __shared__ __align__(16) float Ws[256*16];
    __shared__ float4 s_tb[NLAB];
    __shared__ float  s_ta[NLAB];
    __shared__ int    s_idx[NLAB];
    __shared__ int    s_fidx[NLAB];
    __shared__ float4 s_l4[NLAB];   // fx fy lw lh
    __shared__ float  s_lt[NLAB];   // tscale
    __shared__ float  s_bias[16];
    __shared__ float  s_red[8][3];

    for (int i = tid; i < 15*256; i += 256){
        int s = i >> 8, c = i & 255;
        int a = s/5, j = s - a*5;
        Ws[c*16 + s] = conv_w[(a*NCH + j)*256 + c];
    }
    Ws[tid*16 + 15] = 0.0f;
    if (tid >= 224 && tid < 239){ int s = tid-224; int a = s/5; s_bias[s] = conv_b[a*NCH + (s - a*5)]; }
    if (tid == 239) s_bias[15] = 0.0f;
    if (tid < NLAB){
        const float* L = labels + (size_t)(b*NLAB + tid)*5;
        float tx,ty,tw,th; int bi;
        int idx = label_idx(L, tx,ty,tw,th, bi);
        s_idx[tid] = idx;
        s_tb[tid]  = make_float4(tx - tw*0.5f, ty - th*0.5f, tx + tw*0.5f, ty + th*0.5f);
        s_ta[tid]  = tw*th;
        int ti = (int)tx, tj = (int)ty;
        int sb = (bi < NANCH) ? bi : 0;
        s_l4[tid] = make_float4(tx - (float)ti, ty - (float)tj,
                                logf(tw / c_RW[sb] + 1e-16f),
                                logf(th / c_RH[sb] + 1e-16f));
        s_lt[tid] = 2.0f - tw*th*(1.0f/(float)(FS*FS));
    }
    __syncthreads();

    // parallel last-wins winner selection (writes to separate array, no hazard)
    if (tid < NLAB){
        int idx = s_idx[tid];
        if (idx >= 0)
            for (int j = tid+1; j < NLAB; j++) if (s_idx[j] == idx) { idx = -1; break; }
        s_fidx[tid] = idx;
    }

    unsigned long long accd[8];
    #pragma unroll
    for (int p = 0; p < 8; p++) accd[p] = packff(s_bias[2*p], s_bias[2*p+1]);

    const float* xp = xin + (size_t)b*256*NPIX + pix;
    const ulonglong2* W2 = reinterpret_cast<const ulonglong2*>(Ws);
    #pragma unroll 4
    for (int c = 0; c < 256; c++){
        float x = __ldg(xp + (size_t)c*NPIX);
        unsigned long long xd = packff(x, x);
        ulonglong2 q0 = W2[c*4+0], q1 = W2[c*4+1], q2 = W2[c*4+2], q3 = W2[c*4+3];
        FMA2(accd[0], xd, q0.x); FMA2(accd[1], xd, q0.y);
        FMA2(accd[2], xd, q1.x); FMA2(accd[3], xd, q1.y);
        FMA2(accd[4], xd, q2.x); FMA2(accd[5], xd, q2.y);
        FMA2(accd[6], xd, q3.x); FMA2(accd[7], xd, q3.y);
    }
    float acc[16];
    #pragma unroll
    for (int p = 0; p < 8; p++) unpackff(accd[p], acc[2*p], acc[2*p+1]);
    __syncthreads();   // orders s_fidx writes before epilogue reads

    // per-anchor pred boxes
    const float MAW[3] = {1.25f, 2.0f, 4.125f};
    const float MAH[3] = {1.625f, 3.75f, 2.875f};
    float fw = (float)(pix & 63);
    float fh = (float)(pix >> 6);
    float p0a[3], p1a[3], p4a[3];
    float ax0[3], ay0[3], ax1[3], ay1[3], areaA[3];
    #pragma unroll
    for (int a = 0; a < 3; a++){
        float o0 = acc[a*5+0], o1 = acc[a*5+1], o2 = acc[a*5+2];
        float o3 = acc[a*5+3], o4 = acc[a*5+4];
        p0a[a] = sigm(o0); p1a[a] = sigm(o1); p4a[a] = sigm(o4);
        float pw = expf(o2)*MAW[a], ph = expf(o3)*MAH[a];
        float px = p0a[a] + fw, py = p1a[a] + fh;
        areaA[a] = pw*ph;
        ax0[a] = px - pw*0.5f; ay0[a] = py - ph*0.5f;
        ax1[a] = px + pw*0.5f; ay1[a] = py + ph*0.5f;
    }

    // single pass over truths: ignore mask (3 anchors) + match slots
    int ign = 0;
    int msl[3] = {-1,-1,-1};
    for (int kk = 0; kk < NLAB; kk++){
        float4 t = s_tb[kk];
        float ta = s_ta[kk];
        #pragma unroll
        for (int a = 0; a < 3; a++){
            float iw = fmaxf(fminf(ax1[a], t.z) - fmaxf(ax0[a], t.x), 0.0f);
            float ih = fmaxf(fminf(ay1[a], t.w) - fmaxf(ay0[a], t.y), 0.0f);
            float inter = iw*ih;
            float den   = areaA[a] + ta - inter;
            ign |= (inter > 0.7f*den) << a;
        }
        int e = s_fidx[kk];
        if (e >= 0 && (e & 4095) == pix) msl[e >> 12] = kk;
    }

    float lobj = 0.0f, lxy = 0.0f, lwh = 0.0f;
    #pragma unroll
    for (int a = 0; a < 3; a++){
        int slot = msl[a];
        if (slot >= 0){
            lobj += bcef(p4a[a], 1.0f);
            float4 d = s_l4[slot];
            float ts = s_lt[slot];
            lxy += (bcef(p0a[a], d.x) + bcef(p1a[a], d.y))*ts;
            float dw = acc[a*5+2] - d.z, dh = acc[a*5+3] - d.w;
            lwh += (dw*dw + dh*dh)*0.5f*ts;
        } else if (!((ign >> a) & 1)){
            lobj += bcef(p4a[a], 0.0f);
        }
    }

    lxy = warpsum(lxy); lwh = warpsum(lwh); lobj = warpsum(lobj);
    int wid = tid >> 5, lane = tid & 31;
    if (lane == 0){ s_red[wid][0] = lxy; s_red[wid][1] = lwh; s_red[wid][2] = lobj; }
    __syncthreads();
    if (tid == 0){
        float vx=0.f, vw=0.f, vo=0.f;
        #pragma unroll
        for (int q = 0; q < 8; q++){ vx += s_red[q][0]; vw += s_red[q][1]; vo += s_red[q][2]; }
        g_part[blockIdx.x] = make_float4(vx, vw, vo, 0.f);
    }
}

// ---------------- finalize: reduce per-block partials ----------------
__global__ __launch_bounds__(128) void k_final(float* __restrict__ out){
    int w = threadIdx.x >> 5, lane = threadIdx.x & 31;
    const float* P = (const float*)g_part;
    double s = 0.0;
    for (int i = lane; i < TOTBLK; i += 32) s += (double)P[i*4 + w];
    #pragma unroll
    for (int o = 16; o; o >>= 1) s += __shfl_down_sync(0xffffffffu, s, o);
    __shared__ double sr[4];
    if (lane == 0) sr[w] = s;
    __syncthreads();
    if (threadIdx.x == 0){
        double xy = sr[0], wh = sr[1], obj = sr[2], cls = sr[3];
        out[0] = (float)(xy + wh + obj + cls);
        out[1] = (float)xy;
        out[2] = (float)wh;
        out[3] = (float)obj;
        out[4] = (float)cls;
    }
}

extern "C" void kernel_launch(void* const* d_in, const int* in_sizes, int n_in,
                              void* d_out, int out_size){
    const float* xin    = (const float*)d_in[0];
    const float* labels = (const float*)d_in[1];
    const float* conv_w = (const float*)d_in[2];
    const float* conv_b = (const float*)d_in[3];
    float* out = (float*)d_out;

    k_fused<<<TOTBLK, 256>>>(xin, labels, conv_w, conv_b);
    k_final<<<1, 128>>>(out);
}